// round 13
// baseline (speedup 1.0000x reference)
#include <cuda_runtime.h>
#include <cuda_fp16.h>
#include <cstdint>

#define DI __device__ __forceinline__

// ---------------- problem sizes ----------------
static constexpr int M = 8192;
static constexpr int N = 4096;
static constexpr int K = 4096;

// ---------------- GEMM tiling ----------------
static constexpr int BM = 128;
static constexpr int BN = 128;
static constexpr int KC = 64;                   // 64 halves per K-chunk = 128 B rows
static constexpr int NCHUNK = K / KC;           // 64
static constexpr int NSTAGE = 3;
static constexpr int PITCH = 144;               // 128B row + 16B pad -> conflict-free ldmatrix
static constexpr int A_BYTES = BM * PITCH;      // 18432
static constexpr int B_BYTES = BN * PITCH;      // 18432
static constexpr int STAGE_BYTES = A_BYTES + B_BYTES;        // 36864
static constexpr int SMEM_TOTAL = NSTAGE * STAGE_BYTES;      // 110592 -> 2 CTAs/SM (221KB/228KB)

// ---------------- device scratch ----------------
__device__ __half g_xq[(size_t)M * K];          // fp16 quantized activations (exact ints)
__device__ __half g_wq[(size_t)N * K];          // fp16 ternary weights {-1,0,1}
__device__ float  g_sx[M];
__device__ double g_part[4096];
__device__ float  g_sw;
__device__ float  g_wdenom;

// ---------------- helpers ----------------
DI uint32_t smem_u32(const void* p) {
    uint32_t a;
    asm("{ .reg .u64 t; cvta.to.shared.u64 t, %1; cvt.u32.u64 %0, t; }" : "=r"(a) : "l"(p));
    return a;
}
DI void cp16(uint32_t dst, const void* src) {
    asm volatile("cp.async.cg.shared.global [%0], [%1], 16;"
                 :: "r"(dst), "l"(__cvta_generic_to_global(src)) : "memory");
}
DI void cp_commit() { asm volatile("cp.async.commit_group;" ::: "memory"); }
DI void cp_wait1()  { asm volatile("cp.async.wait_group 1;"  ::: "memory"); }

DI void ldsm_x4(uint32_t* r, uint32_t addr) {
    asm volatile("ldmatrix.sync.aligned.m8n8.x4.shared.b16 {%0,%1,%2,%3}, [%4];"
                 : "=r"(r[0]), "=r"(r[1]), "=r"(r[2]), "=r"(r[3]) : "r"(addr));
}
DI void hmma(float* c, const uint32_t* a, uint32_t b0, uint32_t b1) {
    asm volatile(
        "mma.sync.aligned.m16n8k16.row.col.f32.f16.f16.f32 "
        "{%0,%1,%2,%3}, {%4,%5,%6,%7}, {%8,%9}, {%0,%1,%2,%3};"
        : "+f"(c[0]), "+f"(c[1]), "+f"(c[2]), "+f"(c[3])
        : "r"(a[0]), "r"(a[1]), "r"(a[2]), "r"(a[3]), "r"(b0), "r"(b1));
}
DI uint32_t pack_h2(float a, float b) {
    __half2 t = __floats2half2_rn(a, b);
    return *reinterpret_cast<uint32_t*>(&t);
}

// ==================== merged quant stage 1 (R12, unchanged) ====================

__global__ void k_prep(const float* __restrict__ w, const float* __restrict__ x) {
    if (blockIdx.x < 4096) {
        __shared__ double redd[256];
        const int row = blockIdx.x;
        const float4* p = reinterpret_cast<const float4*>(w + (size_t)row * 4096);
        float s0 = 0.f, s1 = 0.f, s2 = 0.f, s3 = 0.f;
#pragma unroll
        for (int j = 0; j < 4; ++j) {
            float4 v = p[threadIdx.x + j * 256];
            s0 += fabsf(v.x);
            s1 += fabsf(v.y);
            s2 += fabsf(v.z);
            s3 += fabsf(v.w);
        }
        redd[threadIdx.x] = (double)((s0 + s1) + (s2 + s3));
        __syncthreads();
        for (int st = 128; st > 0; st >>= 1) {
            if (threadIdx.x < st) redd[threadIdx.x] += redd[threadIdx.x + st];
            __syncthreads();
        }
        if (threadIdx.x == 0) g_part[row] = redd[0];
    } else {
        __shared__ float red[256];
        __shared__ float s_scale;
        const int row = blockIdx.x - 4096;
        const float4* p = reinterpret_cast<const float4*>(x + (size_t)row * 4096);
        float4 v[4];
        float am = 0.f;
#pragma unroll
        for (int j = 0; j < 4; ++j) {
            v[j] = p[threadIdx.x + j * 256];
            am = fmaxf(am, fmaxf(fmaxf(fabsf(v[j].x), fabsf(v[j].y)),
                                 fmaxf(fabsf(v[j].z), fabsf(v[j].w))));
        }
        red[threadIdx.x] = am;
        __syncthreads();
        for (int st = 128; st > 0; st >>= 1) {
            if (threadIdx.x < st) red[threadIdx.x] = fmaxf(red[threadIdx.x], red[threadIdx.x + st]);
            __syncthreads();
        }
        if (threadIdx.x == 0) {
            float sc = fmaxf(red[0] / 127.0f, 1e-8f);
            s_scale = sc;
            g_sx[row] = sc;
        }
        __syncthreads();
        const float sc = s_scale;
        uint2* out = reinterpret_cast<uint2*>(g_xq + (size_t)row * 4096);
#pragma unroll
        for (int j = 0; j < 4; ++j) {
            float q0 = fminf(fmaxf(rintf(v[j].x / sc), -127.f), 127.f);
            float q1 = fminf(fmaxf(rintf(v[j].y / sc), -127.f), 127.f);
            float q2 = fminf(fmaxf(rintf(v[j].z / sc), -127.f), 127.f);
            float q3 = fminf(fmaxf(rintf(v[j].w / sc), -127.f), 127.f);
            uint2 o;
            o.x = pack_h2(q0, q1);
            o.y = pack_h2(q2, q3);
            out[threadIdx.x + j * 256] = o;
        }
    }
}

__global__ void k_wscale() {
    __shared__ double red[256];
    double s = 0.0;
#pragma unroll
    for (int j = 0; j < 16; ++j) s += g_part[threadIdx.x + j * 256];
    red[threadIdx.x] = s;
    __syncthreads();
    for (int st = 128; st > 0; st >>= 1) {
        if (threadIdx.x < st) red[threadIdx.x] += red[threadIdx.x + st];
        __syncthreads();
    }
    if (threadIdx.x == 0) {
        float sc = (float)(red[0] / 16777216.0);
        g_sw = sc;
        g_wdenom = sc + 1e-8f;
    }
}

__global__ void k_wq(const float* __restrict__ w) {
    const size_t i = (size_t)blockIdx.x * 256 + threadIdx.x;
    float4 v = reinterpret_cast<const float4*>(w)[i];
    const float d = g_wdenom;
    float q0 = fminf(fmaxf(rintf(v.x / d), -1.f), 1.f);
    float q1 = fminf(fmaxf(rintf(v.y / d), -1.f), 1.f);
    float q2 = fminf(fmaxf(rintf(v.z / d), -1.f), 1.f);
    float q3 = fminf(fmaxf(rintf(v.w / d), -1.f), 1.f);
    uint2 o;
    o.x = pack_h2(q0, q1);
    o.y = pack_h2(q2, q3);
    reinterpret_cast<uint2*>(g_wq)[i] = o;
}

// ==================== GEMM ====================
// CTA 128x128x64, 8 warps (2m x 4n), warp tile 64x32, m16n8k16 HMMA, fp32 acc.
// 3-stage ring of 128B-row chunks (barriers halved), B fragments double-buffered
// across ks so hmma groups only wait on their A ldsm. 2 CTAs/SM.

__global__ void __launch_bounds__(256, 2) k_gemm(float* __restrict__ out) {
    extern __shared__ char smem[];
    const uint32_t sb = smem_u32(smem);
    const int tid = threadIdx.x, wid = tid >> 5, lane = tid & 31;
    const int wm = wid & 1, wn = wid >> 1;      // warp grid 2 (m) x 4 (n)

    const int nt = blockIdx.x & 31;             // n fast-varying: W stays L2-hot
    const int mt = blockIdx.x >> 5;

    const char* gA = (const char*)g_xq + (size_t)mt * BM * K * 2;
    const char* gB = (const char*)g_wq + (size_t)nt * BN * K * 2;

    const int rowL = lane & 15;
    const int byteL = (lane >> 4) * 16;
    uint32_t aoff[4], boff[2];
#pragma unroll
    for (int im = 0; im < 4; ++im)
        aoff[im] = (uint32_t)((wm * 64 + im * 16 + rowL) * PITCH + byteL);
#pragma unroll
    for (int ib = 0; ib < 2; ++ib)
        boff[ib] = (uint32_t)(A_BYTES + (wn * 32 + ib * 16 + rowL) * PITCH + byteL);

    float acc[4][4][4];
#pragma unroll
    for (int i = 0; i < 4; ++i)
#pragma unroll
        for (int j = 0; j < 4; ++j)
#pragma unroll
            for (int q = 0; q < 4; ++q) acc[i][j][q] = 0.f;

    auto load_stage = [&](int stage, int kc) {
        const uint32_t base = sb + stage * STAGE_BYTES;
        const size_t koff = (size_t)kc * 128;    // 128 bytes per chunk
#pragma unroll
        for (int i = 0; i < 4; ++i) {            // A: 128 rows x 128B = 1024 segs
            const int idx = tid + i * 256;
            const int r = idx >> 3, c = idx & 7;
            cp16(base + r * PITCH + c * 16, gA + (size_t)r * 8192 + koff + c * 16);
        }
#pragma unroll
        for (int i = 0; i < 4; ++i) {            // B: 128 rows x 128B
            const int idx = tid + i * 256;
            const int r = idx >> 3, c = idx & 7;
            cp16(base + A_BYTES + r * PITCH + c * 16, gB + (size_t)r * 8192 + koff + c * 16);
        }
    };

    load_stage(0, 0); cp_commit();
    load_stage(1, 1); cp_commit();

    int rd = 0, wr = 2;
    for (int kc = 0; kc < NCHUNK; ++kc) {
        cp_wait1();
        __syncthreads();

        if (kc + 2 < NCHUNK) load_stage(wr, kc + 2);
        cp_commit();

        const uint32_t base = sb + rd * STAGE_BYTES;

        uint32_t a[4][4];
        uint32_t bb[2][2][4];                    // [parity][ib][reg]
        // prime B for ks=0
#pragma unroll
        for (int ib = 0; ib < 2; ++ib) ldsm_x4(bb[0][ib], base + boff[ib]);

#pragma unroll
        for (int ks = 0; ks < 4; ++ks) {
            const int cur = ks & 1, nxt = cur ^ 1;
            // A for this step
#pragma unroll
            for (int im = 0; im < 4; ++im) ldsm_x4(a[im], base + aoff[im] + ks * 32);
            // prefetch B for next step (before consuming current B)
            if (ks < 3) {
#pragma unroll
                for (int ib = 0; ib < 2; ++ib)
                    ldsm_x4(bb[nxt][ib], base + boff[ib] + (ks + 1) * 32);
            }
#pragma unroll
            for (int im = 0; im < 4; ++im) {
#pragma unroll
                for (int in = 0; in < 4; ++in) {
                    const int ib = in >> 1, od = in & 1;
                    hmma(acc[im][in], a[im], bb[cur][ib][od ? 1 : 0], bb[cur][ib][od ? 3 : 2]);
                }
            }
        }
        rd = (rd == 2) ? 0 : rd + 1;
        wr = (wr == 2) ? 0 : wr + 1;
    }

    // ---- epilogue: scale by sx[row]*sw and store ----
    const float swv = g_sw;
    const int row0 = mt * BM + wm * 64 + (lane >> 2);
    const int col0 = nt * BN + wn * 32 + 2 * (lane & 3);
#pragma unroll
    for (int im = 0; im < 4; ++im) {
        const int r = row0 + im * 16;
        const float f0 = g_sx[r] * swv;
        const float f8 = g_sx[r + 8] * swv;
        float* po0 = out + (size_t)r * N + col0;
        float* po8 = out + (size_t)(r + 8) * N + col0;
#pragma unroll
        for (int in = 0; in < 4; ++in) {
            float2 v0, v8;
            v0.x = acc[im][in][0] * f0;
            v0.y = acc[im][in][1] * f0;
            v8.x = acc[im][in][2] * f8;
            v8.y = acc[im][in][3] * f8;
            *reinterpret_cast<float2*>(po0 + in * 8) = v0;
            *reinterpret_cast<float2*>(po8 + in * 8) = v8;
        }
    }
}

// ==================== launch ====================
extern "C" void kernel_launch(void* const* d_in, const int* in_sizes, int n_in,
                              void* d_out, int out_size) {
    const float* x = (const float*)d_in[0];
    const float* w = (const float*)d_in[1];
    float* out = (float*)d_out;
    (void)in_sizes; (void)n_in; (void)out_size;

    k_prep<<<4096 + 8192, 256>>>(w, x);
    k_wscale<<<1, 256>>>();
    k_wq<<<16384, 256>>>(w);

    cudaFuncSetAttribute(k_gemm, cudaFuncAttributeMaxDynamicSharedMemorySize, SMEM_TOTAL);
    k_gemm<<<(M / BM) * (N / BN), 256, SMEM_TOTAL>>>(out);
}

// round 14
// speedup vs baseline: 1.2416x; 1.2416x over previous
#include <cuda_runtime.h>
#include <cuda_fp16.h>
#include <cstdint>

#define DI __device__ __forceinline__

// ---------------- problem sizes ----------------
static constexpr int M = 8192;
static constexpr int N = 4096;
static constexpr int K = 4096;

// ---------------- GEMM tiling ----------------
static constexpr int BM = 128;
static constexpr int BN = 128;
static constexpr int KC = 64;                     // halves per chunk = 128B rows
static constexpr int NCHUNK = K / KC;             // 64
static constexpr int NSTAGE = 3;
static constexpr int TILE_BYTES = 128 * 128;      // 16 KB tile (128 rows x 128B, swizzled)
static constexpr int STAGE_BYTES = 2 * TILE_BYTES;             // A + B
static constexpr int SMEM_MBAR = NSTAGE * STAGE_BYTES;         // 98304
static constexpr int SMEM_TOTAL = SMEM_MBAR + 64;              // + mbarriers -> 2 CTAs/SM

// ---------------- device scratch (tiled + swizzled layouts) ----------------
// g_xq: [mt(64)][kc(64)][rr(128)][sw16B(8)]  g_wq: [nt(32)][kc(64)][...]
__device__ __half g_xq[(size_t)M * K];
__device__ __half g_wq[(size_t)N * K];
__device__ float  g_sx[M];
__device__ double g_part[4096];
__device__ float  g_sw;
__device__ float  g_wdenom;

// ---------------- helpers ----------------
DI uint32_t smem_u32(const void* p) {
    uint32_t a;
    asm("{ .reg .u64 t; cvta.to.shared.u64 t, %1; cvt.u32.u64 %0, t; }" : "=r"(a) : "l"(p));
    return a;
}
DI void mbar_init(uint32_t addr, uint32_t cnt) {
    asm volatile("mbarrier.init.shared.b64 [%0], %1;" :: "r"(addr), "r"(cnt) : "memory");
}
DI void mbar_arrive(uint32_t addr) {
    asm volatile("mbarrier.arrive.shared.b64 _, [%0];" :: "r"(addr) : "memory");
}
DI void mbar_expect_tx(uint32_t addr, uint32_t bytes) {
    asm volatile("mbarrier.arrive.expect_tx.shared.b64 _, [%0], %1;"
                 :: "r"(addr), "r"(bytes) : "memory");
}
DI void mbar_wait(uint32_t addr, uint32_t parity) {
    asm volatile(
        "{\n\t.reg .pred P;\n\t"
        "WL%=:\n\t"
        "mbarrier.try_wait.parity.acquire.cta.shared::cta.b64 P, [%0], %1, 0x989680;\n\t"
        "@P bra.uni WD%=;\n\t"
        "bra.uni WL%=;\n\t"
        "WD%=:\n\t}"
        :: "r"(addr), "r"(parity) : "memory");
}
// one 16KB bulk DMA global->shared, completion via mbarrier tx-bytes
DI void bulk16k(uint32_t dst, const void* src, uint32_t mbar) {
    asm volatile(
        "cp.async.bulk.shared::cluster.global.mbarrier::complete_tx::bytes [%0], [%1], %2, [%3];"
        :: "r"(dst), "l"(__cvta_generic_to_global(src)), "r"((uint32_t)TILE_BYTES), "r"(mbar)
        : "memory");
}
DI void ldsm_x4(uint32_t* r, uint32_t addr) {
    asm volatile("ldmatrix.sync.aligned.m8n8.x4.shared.b16 {%0,%1,%2,%3}, [%4];"
                 : "=r"(r[0]), "=r"(r[1]), "=r"(r[2]), "=r"(r[3]) : "r"(addr));
}
DI void hmma(float* c, const uint32_t* a, uint32_t b0, uint32_t b1) {
    asm volatile(
        "mma.sync.aligned.m16n8k16.row.col.f32.f16.f16.f32 "
        "{%0,%1,%2,%3}, {%4,%5,%6,%7}, {%8,%9}, {%0,%1,%2,%3};"
        : "+f"(c[0]), "+f"(c[1]), "+f"(c[2]), "+f"(c[3])
        : "r"(a[0]), "r"(a[1]), "r"(a[2]), "r"(a[3]), "r"(b0), "r"(b1));
}
DI uint32_t pack_h2(float a, float b) {
    __half2 t = __floats2half2_rn(a, b);
    return *reinterpret_cast<uint32_t*>(&t);
}
// quantize 8 floats -> uint4 of packed halves
DI uint4 quant8(float4 a, float4 b, float inv_den_is_div, float den, float lo, float hi2) {
    (void)inv_den_is_div;
    uint4 o;
    float q0 = fminf(fmaxf(rintf(a.x / den), lo), hi2);
    float q1 = fminf(fmaxf(rintf(a.y / den), lo), hi2);
    float q2 = fminf(fmaxf(rintf(a.z / den), lo), hi2);
    float q3 = fminf(fmaxf(rintf(a.w / den), lo), hi2);
    float q4 = fminf(fmaxf(rintf(b.x / den), lo), hi2);
    float q5 = fminf(fmaxf(rintf(b.y / den), lo), hi2);
    float q6 = fminf(fmaxf(rintf(b.z / den), lo), hi2);
    float q7 = fminf(fmaxf(rintf(b.w / den), lo), hi2);
    o.x = pack_h2(q0, q1);
    o.y = pack_h2(q2, q3);
    o.z = pack_h2(q4, q5);
    o.w = pack_h2(q6, q7);
    return o;
}

// ==================== quant stage 1: wabs (blocks 0..4095) || xq (blocks 4096..12287) ====================

__global__ void k_prep(const float* __restrict__ w, const float* __restrict__ x) {
    const int t = threadIdx.x;
    if (blockIdx.x < 4096) {
        __shared__ double redd[256];
        const int row = blockIdx.x;
        const float4* p = reinterpret_cast<const float4*>(w + (size_t)row * 4096);
        float s0 = 0.f, s1 = 0.f, s2 = 0.f, s3 = 0.f;
#pragma unroll
        for (int j = 0; j < 4; ++j) {
            float4 v = p[t + j * 256];
            s0 += fabsf(v.x);
            s1 += fabsf(v.y);
            s2 += fabsf(v.z);
            s3 += fabsf(v.w);
        }
        redd[t] = (double)((s0 + s1) + (s2 + s3));
        __syncthreads();
        for (int st = 128; st > 0; st >>= 1) {
            if (t < st) redd[t] += redd[t + st];
            __syncthreads();
        }
        if (t == 0) g_part[row] = redd[0];
    } else {
        __shared__ float red[256];
        __shared__ float s_scale;
        const int row = blockIdx.x - 4096;
        const float4* p = reinterpret_cast<const float4*>(x + (size_t)row * 4096);
        float4 v[4];
        v[0] = p[2 * t];
        v[1] = p[2 * t + 1];
        v[2] = p[2 * t + 512];
        v[3] = p[2 * t + 513];
        float am = 0.f;
#pragma unroll
        for (int j = 0; j < 4; ++j)
            am = fmaxf(am, fmaxf(fmaxf(fabsf(v[j].x), fabsf(v[j].y)),
                                 fmaxf(fabsf(v[j].z), fabsf(v[j].w))));
        red[t] = am;
        __syncthreads();
        for (int st = 128; st > 0; st >>= 1) {
            if (t < st) red[t] = fmaxf(red[t], red[t + st]);
            __syncthreads();
        }
        if (t == 0) {
            float sc = fmaxf(red[0] / 127.0f, 1e-8f);
            s_scale = sc;
            g_sx[row] = sc;
        }
        __syncthreads();
        const float sc = s_scale;
        char* tbase = (char*)g_xq + (size_t)(row >> 7) * 64 * TILE_BYTES;
        const int rr = row & 127;
        const int sw = rr & 7;
#pragma unroll
        for (int j = 0; j < 2; ++j) {
            uint4 o = quant8(v[2 * j], v[2 * j + 1], 0.f, sc, -127.f, 127.f);
            const int u = t + 256 * j;       // 16B unit index within row (0..511)
            const int kc = u >> 3, c = u & 7;
            *reinterpret_cast<uint4*>(tbase + (size_t)kc * TILE_BYTES + rr * 128 +
                                      ((c ^ sw) << 4)) = o;
        }
    }
}

__global__ void k_wscale() {
    __shared__ double red[256];
    double s = 0.0;
#pragma unroll
    for (int j = 0; j < 16; ++j) s += g_part[threadIdx.x + j * 256];
    red[threadIdx.x] = s;
    __syncthreads();
    for (int st = 128; st > 0; st >>= 1) {
        if (threadIdx.x < st) red[threadIdx.x] += red[threadIdx.x + st];
        __syncthreads();
    }
    if (threadIdx.x == 0) {
        float sc = (float)(red[0] / 16777216.0);
        g_sw = sc;
        g_wdenom = sc + 1e-8f;
    }
}

// W ternarize into tiled+swizzled layout; one block per weight row
__global__ void k_wq(const float* __restrict__ w) {
    const int t = threadIdx.x;
    const int row = blockIdx.x;
    const float4* p = reinterpret_cast<const float4*>(w + (size_t)row * 4096);
    float4 v[4];
    v[0] = p[2 * t];
    v[1] = p[2 * t + 1];
    v[2] = p[2 * t + 512];
    v[3] = p[2 * t + 513];
    const float d = g_wdenom;
    char* tbase = (char*)g_wq + (size_t)(row >> 7) * 64 * TILE_BYTES;
    const int rr = row & 127;
    const int sw = rr & 7;
#pragma unroll
    for (int j = 0; j < 2; ++j) {
        uint4 o = quant8(v[2 * j], v[2 * j + 1], 0.f, d, -1.f, 1.f);
        const int u = t + 256 * j;
        const int kc = u >> 3, c = u & 7;
        *reinterpret_cast<uint4*>(tbase + (size_t)kc * TILE_BYTES + rr * 128 +
                                  ((c ^ sw) << 4)) = o;
    }
}

// ==================== GEMM ====================
// CTA 128x128x64, 8 warps (2m x 4n), warp tile 64x32, m16n8k16 HMMA, fp32 acc.
// 3-stage mbarrier ring fed by cp.async.bulk (one 16KB DMA per operand per chunk) —
// no per-thread copies, no L1tex wavefront pollution. Tiles pre-swizzled (SW128)
// in gmem so pitch-128 ldsm is conflict-free. 2 CTAs/SM.

__global__ void __launch_bounds__(256, 2) k_gemm(float* __restrict__ out) {
    extern __shared__ char smem[];
    const uint32_t sb = smem_u32(smem);
    const uint32_t mb = sb + SMEM_MBAR;           // full[3] @ +0,8,16 ; empty[3] @ +24,32,40
    const int tid = threadIdx.x, wid = tid >> 5, lane = tid & 31;
    const int wm = wid & 1, wn = wid >> 1;        // warp grid 2 (m) x 4 (n)

    const int nt = blockIdx.x & 31;               // n fast-varying: W stays L2-hot
    const int mt = blockIdx.x >> 5;

    if (tid == 0) {
#pragma unroll
        for (int s = 0; s < NSTAGE; ++s) {
            mbar_init(mb + s * 8, 1);             // full: 1 producer arrival (expect_tx)
            mbar_init(mb + 24 + s * 8, 8);        // empty: 8 warp arrivals
        }
    }
    __syncthreads();

    const char* srcA = (const char*)g_xq + (size_t)mt * 64 * TILE_BYTES;
    const char* srcB = (const char*)g_wq + (size_t)nt * 64 * TILE_BYTES;

    // producer prologue: fill all 3 stages
    if (tid == 0) {
#pragma unroll
        for (int s = 0; s < NSTAGE; ++s) {
            mbar_expect_tx(mb + s * 8, STAGE_BYTES);
            bulk16k(sb + s * STAGE_BYTES, srcA + (size_t)s * TILE_BYTES, mb + s * 8);
            bulk16k(sb + s * STAGE_BYTES + TILE_BYTES, srcB + (size_t)s * TILE_BYTES,
                    mb + s * 8);
        }
    }

    // fragment address precompute (swizzle: 16B col c' = c ^ (row&7), c = 2ks+hi)
    const int rowL = lane & 15, hi = lane >> 4;
    uint32_t abase[4], as6[4], bbase[2], bs6[2];
#pragma unroll
    for (int im = 0; im < 4; ++im) {
        const int r = wm * 64 + im * 16 + rowL;
        const int s = r & 7;
        abase[im] = (uint32_t)(r * 128 + ((hi ^ (s & 1)) << 4));
        as6[im] = (uint32_t)((s & 6) << 4);
    }
#pragma unroll
    for (int ib = 0; ib < 2; ++ib) {
        const int r = wn * 32 + ib * 16 + rowL;
        const int s = r & 7;
        bbase[ib] = (uint32_t)(TILE_BYTES + r * 128 + ((hi ^ (s & 1)) << 4));
        bs6[ib] = (uint32_t)((s & 6) << 4);
    }

    float acc[4][4][4];
#pragma unroll
    for (int i = 0; i < 4; ++i)
#pragma unroll
        for (int j = 0; j < 4; ++j)
#pragma unroll
            for (int q = 0; q < 4; ++q) acc[i][j][q] = 0.f;

    int stage = 0, phase = 0;
    for (int kc = 0; kc < NCHUNK; ++kc) {
        const uint32_t stg = sb + stage * STAGE_BYTES;
        mbar_wait(mb + stage * 8, phase);         // data ready

#pragma unroll
        for (int ks = 0; ks < 4; ++ks) {
            const uint32_t kterm = 32u * ks;
            uint32_t a[4][4], b[2][4];
#pragma unroll
            for (int im = 0; im < 4; ++im)
                ldsm_x4(a[im], stg + abase[im] + (kterm ^ as6[im]));
#pragma unroll
            for (int ib = 0; ib < 2; ++ib)
                ldsm_x4(b[ib], stg + bbase[ib] + (kterm ^ bs6[ib]));
#pragma unroll
            for (int im = 0; im < 4; ++im) {
#pragma unroll
                for (int in = 0; in < 4; ++in) {
                    const int ib = in >> 1, od = in & 1;
                    hmma(acc[im][in], a[im], b[ib][od ? 1 : 0], b[ib][od ? 3 : 2]);
                }
            }
        }

        if (lane == 0) mbar_arrive(mb + 24 + stage * 8);      // this warp done reading

        if (tid == 0 && kc + NSTAGE < NCHUNK) {
            mbar_wait(mb + 24 + stage * 8, phase);            // all 8 warps done
            mbar_expect_tx(mb + stage * 8, STAGE_BYTES);
            bulk16k(stg, srcA + (size_t)(kc + NSTAGE) * TILE_BYTES, mb + stage * 8);
            bulk16k(stg + TILE_BYTES, srcB + (size_t)(kc + NSTAGE) * TILE_BYTES,
                    mb + stage * 8);
        }

        if (++stage == NSTAGE) { stage = 0; phase ^= 1; }
    }

    // ---- epilogue: scale by sx[row]*sw and store ----
    const float swv = g_sw;
    const int row0 = mt * BM + wm * 64 + (lane >> 2);
    const int col0 = nt * BN + wn * 32 + 2 * (lane & 3);
#pragma unroll
    for (int im = 0; im < 4; ++im) {
        const int r = row0 + im * 16;
        const float f0 = g_sx[r] * swv;
        const float f8 = g_sx[r + 8] * swv;
        float* po0 = out + (size_t)r * N + col0;
        float* po8 = out + (size_t)(r + 8) * N + col0;
#pragma unroll
        for (int in = 0; in < 4; ++in) {
            float2 v0, v8;
            v0.x = acc[im][in][0] * f0;
            v0.y = acc[im][in][1] * f0;
            v8.x = acc[im][in][2] * f8;
            v8.y = acc[im][in][3] * f8;
            *reinterpret_cast<float2*>(po0 + in * 8) = v0;
            *reinterpret_cast<float2*>(po8 + in * 8) = v8;
        }
    }
}

// ==================== launch ====================
extern "C" void kernel_launch(void* const* d_in, const int* in_sizes, int n_in,
                              void* d_out, int out_size) {
    const float* x = (const float*)d_in[0];
    const float* w = (const float*)d_in[1];
    float* out = (float*)d_out;
    (void)in_sizes; (void)n_in; (void)out_size;

    k_prep<<<4096 + 8192, 256>>>(w, x);
    k_wscale<<<1, 256>>>();
    k_wq<<<4096, 256>>>(w);

    cudaFuncSetAttribute(k_gemm, cudaFuncAttributeMaxDynamicSharedMemorySize, SMEM_TOTAL);
    k_gemm<<<(M / BM) * (N / BN), 256, SMEM_TOTAL>>>(out);
}

// round 15
// speedup vs baseline: 1.2524x; 1.0087x over previous
#include <cuda_runtime.h>
#include <cuda_fp16.h>
#include <cstdint>

#define DI __device__ __forceinline__

// ---------------- problem sizes ----------------
static constexpr int M = 8192;
static constexpr int N = 4096;
static constexpr int K = 4096;

// ---------------- GEMM tiling ----------------
static constexpr int BM = 128;
static constexpr int BN = 128;
static constexpr int KC = 64;                     // halves per chunk = 128B rows
static constexpr int NCHUNK = K / KC;             // 64
static constexpr int NSTAGE = 3;
static constexpr int TILE_BYTES = 128 * 128;      // 16 KB tile (128 rows x 128B, swizzled)
static constexpr int STAGE_BYTES = 2 * TILE_BYTES;             // A + B
static constexpr int SMEM_MBAR = NSTAGE * STAGE_BYTES;         // 98304
static constexpr int SMEM_TOTAL = SMEM_MBAR + 64;              // + mbarriers -> 2 CTAs/SM

// ---------------- device scratch (tiled + swizzled layouts) ----------------
// g_xq: [mt(64)][kc(64)][rr(128)][sw16B(8)]  g_wq: [nt(32)][kc(64)][...]
__device__ __half g_xq[(size_t)M * K];
__device__ __half g_wq[(size_t)N * K];
__device__ float  g_sx[M];
__device__ double g_part[4096];
__device__ float  g_sw;
__device__ float  g_wdenom;

// ---------------- helpers ----------------
DI uint32_t smem_u32(const void* p) {
    uint32_t a;
    asm("{ .reg .u64 t; cvta.to.shared.u64 t, %1; cvt.u32.u64 %0, t; }" : "=r"(a) : "l"(p));
    return a;
}
DI void mbar_init(uint32_t addr, uint32_t cnt) {
    asm volatile("mbarrier.init.shared.b64 [%0], %1;" :: "r"(addr), "r"(cnt) : "memory");
}
DI void mbar_arrive(uint32_t addr) {
    asm volatile("mbarrier.arrive.shared.b64 _, [%0];" :: "r"(addr) : "memory");
}
DI void mbar_expect_tx(uint32_t addr, uint32_t bytes) {
    asm volatile("mbarrier.arrive.expect_tx.shared.b64 _, [%0], %1;"
                 :: "r"(addr), "r"(bytes) : "memory");
}
DI void mbar_wait(uint32_t addr, uint32_t parity) {
    asm volatile(
        "{\n\t.reg .pred P;\n\t"
        "WL%=:\n\t"
        "mbarrier.try_wait.parity.acquire.cta.shared::cta.b64 P, [%0], %1, 0x989680;\n\t"
        "@P bra.uni WD%=;\n\t"
        "bra.uni WL%=;\n\t"
        "WD%=:\n\t}"
        :: "r"(addr), "r"(parity) : "memory");
}
DI void bulk16k(uint32_t dst, const void* src, uint32_t mbar) {
    asm volatile(
        "cp.async.bulk.shared::cluster.global.mbarrier::complete_tx::bytes [%0], [%1], %2, [%3];"
        :: "r"(dst), "l"(__cvta_generic_to_global(src)), "r"((uint32_t)TILE_BYTES), "r"(mbar)
        : "memory");
}
DI void ldsm_x4(uint32_t* r, uint32_t addr) {
    asm volatile("ldmatrix.sync.aligned.m8n8.x4.shared.b16 {%0,%1,%2,%3}, [%4];"
                 : "=r"(r[0]), "=r"(r[1]), "=r"(r[2]), "=r"(r[3]) : "r"(addr));
}
DI void hmma(float* c, const uint32_t* a, uint32_t b0, uint32_t b1) {
    asm volatile(
        "mma.sync.aligned.m16n8k16.row.col.f32.f16.f16.f32 "
        "{%0,%1,%2,%3}, {%4,%5,%6,%7}, {%8,%9}, {%0,%1,%2,%3};"
        : "+f"(c[0]), "+f"(c[1]), "+f"(c[2]), "+f"(c[3])
        : "r"(a[0]), "r"(a[1]), "r"(a[2]), "r"(a[3]), "r"(b0), "r"(b1));
}
DI uint32_t pack_h2(float a, float b) {
    __half2 t = __floats2half2_rn(a, b);
    return *reinterpret_cast<uint32_t*>(&t);
}
DI uint4 quant8(float4 a, float4 b, float den, float lo, float hi2) {
    uint4 o;
    float q0 = fminf(fmaxf(rintf(a.x / den), lo), hi2);
    float q1 = fminf(fmaxf(rintf(a.y / den), lo), hi2);
    float q2 = fminf(fmaxf(rintf(a.z / den), lo), hi2);
    float q3 = fminf(fmaxf(rintf(a.w / den), lo), hi2);
    float q4 = fminf(fmaxf(rintf(b.x / den), lo), hi2);
    float q5 = fminf(fmaxf(rintf(b.y / den), lo), hi2);
    float q6 = fminf(fmaxf(rintf(b.z / den), lo), hi2);
    float q7 = fminf(fmaxf(rintf(b.w / den), lo), hi2);
    o.x = pack_h2(q0, q1);
    o.y = pack_h2(q2, q3);
    o.z = pack_h2(q4, q5);
    o.w = pack_h2(q6, q7);
    return o;
}

// ==================== quant stage 1 (R14, unchanged) ====================

__global__ void k_prep(const float* __restrict__ w, const float* __restrict__ x) {
    const int t = threadIdx.x;
    if (blockIdx.x < 4096) {
        __shared__ double redd[256];
        const int row = blockIdx.x;
        const float4* p = reinterpret_cast<const float4*>(w + (size_t)row * 4096);
        float s0 = 0.f, s1 = 0.f, s2 = 0.f, s3 = 0.f;
#pragma unroll
        for (int j = 0; j < 4; ++j) {
            float4 v = p[t + j * 256];
            s0 += fabsf(v.x);
            s1 += fabsf(v.y);
            s2 += fabsf(v.z);
            s3 += fabsf(v.w);
        }
        redd[t] = (double)((s0 + s1) + (s2 + s3));
        __syncthreads();
        for (int st = 128; st > 0; st >>= 1) {
            if (t < st) redd[t] += redd[t + st];
            __syncthreads();
        }
        if (t == 0) g_part[row] = redd[0];
    } else {
        __shared__ float red[256];
        __shared__ float s_scale;
        const int row = blockIdx.x - 4096;
        const float4* p = reinterpret_cast<const float4*>(x + (size_t)row * 4096);
        float4 v[4];
        v[0] = p[2 * t];
        v[1] = p[2 * t + 1];
        v[2] = p[2 * t + 512];
        v[3] = p[2 * t + 513];
        float am = 0.f;
#pragma unroll
        for (int j = 0; j < 4; ++j)
            am = fmaxf(am, fmaxf(fmaxf(fabsf(v[j].x), fabsf(v[j].y)),
                                 fmaxf(fabsf(v[j].z), fabsf(v[j].w))));
        red[t] = am;
        __syncthreads();
        for (int st = 128; st > 0; st >>= 1) {
            if (t < st) red[t] = fmaxf(red[t], red[t + st]);
            __syncthreads();
        }
        if (t == 0) {
            float sc = fmaxf(red[0] / 127.0f, 1e-8f);
            s_scale = sc;
            g_sx[row] = sc;
        }
        __syncthreads();
        const float sc = s_scale;
        char* tbase = (char*)g_xq + (size_t)(row >> 7) * 64 * TILE_BYTES;
        const int rr = row & 127;
        const int sw = rr & 7;
#pragma unroll
        for (int j = 0; j < 2; ++j) {
            uint4 o = quant8(v[2 * j], v[2 * j + 1], sc, -127.f, 127.f);
            const int u = t + 256 * j;
            const int kc = u >> 3, c = u & 7;
            *reinterpret_cast<uint4*>(tbase + (size_t)kc * TILE_BYTES + rr * 128 +
                                      ((c ^ sw) << 4)) = o;
        }
    }
}

__global__ void k_wscale() {
    __shared__ double red[256];
    double s = 0.0;
#pragma unroll
    for (int j = 0; j < 16; ++j) s += g_part[threadIdx.x + j * 256];
    red[threadIdx.x] = s;
    __syncthreads();
    for (int st = 128; st > 0; st >>= 1) {
        if (threadIdx.x < st) red[threadIdx.x] += red[threadIdx.x + st];
        __syncthreads();
    }
    if (threadIdx.x == 0) {
        float sc = (float)(red[0] / 16777216.0);
        g_sw = sc;
        g_wdenom = sc + 1e-8f;
    }
}

__global__ void k_wq(const float* __restrict__ w) {
    const int t = threadIdx.x;
    const int row = blockIdx.x;
    const float4* p = reinterpret_cast<const float4*>(w + (size_t)row * 4096);
    float4 v[4];
    v[0] = p[2 * t];
    v[1] = p[2 * t + 1];
    v[2] = p[2 * t + 512];
    v[3] = p[2 * t + 513];
    const float d = g_wdenom;
    char* tbase = (char*)g_wq + (size_t)(row >> 7) * 64 * TILE_BYTES;
    const int rr = row & 127;
    const int sw = rr & 7;
#pragma unroll
    for (int j = 0; j < 2; ++j) {
        uint4 o = quant8(v[2 * j], v[2 * j + 1], d, -1.f, 1.f);
        const int u = t + 256 * j;
        const int kc = u >> 3, c = u & 7;
        *reinterpret_cast<uint4*>(tbase + (size_t)kc * TILE_BYTES + rr * 128 +
                                  ((c ^ sw) << 4)) = o;
    }
}

// ==================== GEMM ====================
// CTA 128x128x64, 4 warps (2m x 2n), warp tile 64x64, m16n8k16 HMMA, fp32 acc.
// 3-stage mbarrier ring fed by cp.async.bulk. Fragment re-reads drop to
// (A x2 + B x2) = 64KB/chunk/CTA -> crossbar below tensor floor. 2 CTAs/SM,
// 8 warps/SM; RF allows 256 regs/thread so 128-reg accumulators don't spill.

__global__ void __launch_bounds__(128, 2) k_gemm(float* __restrict__ out) {
    extern __shared__ char smem[];
    const uint32_t sb = smem_u32(smem);
    const uint32_t mb = sb + SMEM_MBAR;           // full[3] @ +0,8,16 ; empty[3] @ +24,32,40
    const int tid = threadIdx.x, wid = tid >> 5, lane = tid & 31;
    const int wm = wid & 1, wn = wid >> 1;        // warp grid 2 (m) x 2 (n)

    const int nt = blockIdx.x & 31;               // n fast-varying: W stays L2-hot
    const int mt = blockIdx.x >> 5;

    if (tid == 0) {
#pragma unroll
        for (int s = 0; s < NSTAGE; ++s) {
            mbar_init(mb + s * 8, 1);             // full: producer expect_tx arrival
            mbar_init(mb + 24 + s * 8, 4);        // empty: 4 warp arrivals
        }
    }
    __syncthreads();

    const char* srcA = (const char*)g_xq + (size_t)mt * 64 * TILE_BYTES;
    const char* srcB = (const char*)g_wq + (size_t)nt * 64 * TILE_BYTES;

    if (tid == 0) {
#pragma unroll
        for (int s = 0; s < NSTAGE; ++s) {
            mbar_expect_tx(mb + s * 8, STAGE_BYTES);
            bulk16k(sb + s * STAGE_BYTES, srcA + (size_t)s * TILE_BYTES, mb + s * 8);
            bulk16k(sb + s * STAGE_BYTES + TILE_BYTES, srcB + (size_t)s * TILE_BYTES,
                    mb + s * 8);
        }
    }

    // fragment address precompute (pre-swizzled tiles: 16B col c' = c ^ (row&7))
    const int rowL = lane & 15, hi = lane >> 4;
    uint32_t abase[4], as6[4], bbase[4], bs6[4];
#pragma unroll
    for (int im = 0; im < 4; ++im) {
        const int r = wm * 64 + im * 16 + rowL;
        const int s = r & 7;
        abase[im] = (uint32_t)(r * 128 + ((hi ^ (s & 1)) << 4));
        as6[im] = (uint32_t)((s & 6) << 4);
    }
#pragma unroll
    for (int ib = 0; ib < 4; ++ib) {
        const int r = wn * 64 + ib * 16 + rowL;
        const int s = r & 7;
        bbase[ib] = (uint32_t)(TILE_BYTES + r * 128 + ((hi ^ (s & 1)) << 4));
        bs6[ib] = (uint32_t)((s & 6) << 4);
    }

    float acc[4][8][4];
#pragma unroll
    for (int i = 0; i < 4; ++i)
#pragma unroll
        for (int j = 0; j < 8; ++j)
#pragma unroll
            for (int q = 0; q < 4; ++q) acc[i][j][q] = 0.f;

    int stage = 0, phase = 0;
    for (int kc = 0; kc < NCHUNK; ++kc) {
        const uint32_t stg = sb + stage * STAGE_BYTES;
        mbar_wait(mb + stage * 8, phase);

#pragma unroll
        for (int ks = 0; ks < 4; ++ks) {
            const uint32_t kterm = 32u * ks;
            uint32_t a[4][4], b[4][4];
#pragma unroll
            for (int im = 0; im < 4; ++im)
                ldsm_x4(a[im], stg + abase[im] + (kterm ^ as6[im]));
#pragma unroll
            for (int ib = 0; ib < 4; ++ib)
                ldsm_x4(b[ib], stg + bbase[ib] + (kterm ^ bs6[ib]));
#pragma unroll
            for (int im = 0; im < 4; ++im) {
#pragma unroll
                for (int in = 0; in < 8; ++in) {
                    const int ib = in >> 1, od = in & 1;
                    hmma(acc[im][in], a[im], b[ib][od ? 1 : 0], b[ib][od ? 3 : 2]);
                }
            }
        }

        if (lane == 0) mbar_arrive(mb + 24 + stage * 8);

        if (tid == 0 && kc + NSTAGE < NCHUNK) {
            mbar_wait(mb + 24 + stage * 8, phase);
            mbar_expect_tx(mb + stage * 8, STAGE_BYTES);
            bulk16k(stg, srcA + (size_t)(kc + NSTAGE) * TILE_BYTES, mb + stage * 8);
            bulk16k(stg + TILE_BYTES, srcB + (size_t)(kc + NSTAGE) * TILE_BYTES,
                    mb + stage * 8);
        }

        if (++stage == NSTAGE) { stage = 0; phase ^= 1; }
    }

    // ---- epilogue: scale by sx[row]*sw and store ----
    const float swv = g_sw;
    const int row0 = mt * BM + wm * 64 + (lane >> 2);
    const int col0 = nt * BN + wn * 64 + 2 * (lane & 3);
#pragma unroll
    for (int im = 0; im < 4; ++im) {
        const int r = row0 + im * 16;
        const float f0 = g_sx[r] * swv;
        const float f8 = g_sx[r + 8] * swv;
        float* po0 = out + (size_t)r * N + col0;
        float* po8 = out + (size_t)(r + 8) * N + col0;
#pragma unroll
        for (int in = 0; in < 8; ++in) {
            float2 v0, v8;
            v0.x = acc[im][in][0] * f0;
            v0.y = acc[im][in][1] * f0;
            v8.x = acc[im][in][2] * f8;
            v8.y = acc[im][in][3] * f8;
            *reinterpret_cast<float2*>(po0 + in * 8) = v0;
            *reinterpret_cast<float2*>(po8 + in * 8) = v8;
        }
    }
}

// ==================== launch ====================
extern "C" void kernel_launch(void* const* d_in, const int* in_sizes, int n_in,
                              void* d_out, int out_size) {
    const float* x = (const float*)d_in[0];
    const float* w = (const float*)d_in[1];
    float* out = (float*)d_out;
    (void)in_sizes; (void)n_in; (void)out_size;

    k_prep<<<4096 + 8192, 256>>>(w, x);
    k_wscale<<<1, 256>>>();
    k_wq<<<4096, 256>>>(w);

    cudaFuncSetAttribute(k_gemm, cudaFuncAttributeMaxDynamicSharedMemorySize, SMEM_TOTAL);
    k_gemm<<<(M / BM) * (N / BN), 128, SMEM_TOTAL>>>(out);
}

// round 16
// speedup vs baseline: 1.4196x; 1.1334x over previous
#include <cuda_runtime.h>
#include <cuda_fp16.h>
#include <cstdint>

#define DI __device__ __forceinline__

// ---------------- problem sizes ----------------
static constexpr int M = 8192;
static constexpr int N = 4096;
static constexpr int K = 4096;

// ---------------- GEMM tiling ----------------
static constexpr int BM = 128;
static constexpr int BN = 128;
static constexpr int KC = 64;                     // halves per chunk = 128B rows
static constexpr int NCHUNK = K / KC;             // 64
static constexpr int NSTAGE = 3;
static constexpr int TILE_BYTES = 128 * 128;      // 16 KB tile (128 rows x 128B, swizzled)
static constexpr int STAGE_BYTES = 2 * TILE_BYTES;             // A + B
static constexpr int SMEM_MBAR = NSTAGE * STAGE_BYTES;         // 98304
static constexpr int SMEM_TOTAL = SMEM_MBAR + 64;              // + mbarriers -> 2 CTAs/SM

// ---------------- device scratch (tiled + swizzled layouts) ----------------
// g_xq: [mt(64)][kc(64)][rr(128)][sw16B(8)]  g_wq: [nt(32)][kc(64)][...]
__device__ __half g_xq[(size_t)M * K];
__device__ __half g_wq[(size_t)N * K];
__device__ float  g_sx[M];
__device__ double g_part[4096];
__device__ float  g_sw;
__device__ float  g_wdenom;

// ---------------- helpers ----------------
DI uint32_t smem_u32(const void* p) {
    uint32_t a;
    asm("{ .reg .u64 t; cvta.to.shared.u64 t, %1; cvt.u32.u64 %0, t; }" : "=r"(a) : "l"(p));
    return a;
}
DI void mbar_init(uint32_t addr, uint32_t cnt) {
    asm volatile("mbarrier.init.shared.b64 [%0], %1;" :: "r"(addr), "r"(cnt) : "memory");
}
DI void mbar_arrive(uint32_t addr) {
    asm volatile("mbarrier.arrive.shared.b64 _, [%0];" :: "r"(addr) : "memory");
}
DI void mbar_expect_tx(uint32_t addr, uint32_t bytes) {
    asm volatile("mbarrier.arrive.expect_tx.shared.b64 _, [%0], %1;"
                 :: "r"(addr), "r"(bytes) : "memory");
}
DI void mbar_wait(uint32_t addr, uint32_t parity) {
    asm volatile(
        "{\n\t.reg .pred P;\n\t"
        "WL%=:\n\t"
        "mbarrier.try_wait.parity.acquire.cta.shared::cta.b64 P, [%0], %1, 0x989680;\n\t"
        "@P bra.uni WD%=;\n\t"
        "bra.uni WL%=;\n\t"
        "WD%=:\n\t}"
        :: "r"(addr), "r"(parity) : "memory");
}
DI void bulk16k(uint32_t dst, const void* src, uint32_t mbar) {
    asm volatile(
        "cp.async.bulk.shared::cluster.global.mbarrier::complete_tx::bytes [%0], [%1], %2, [%3];"
        :: "r"(dst), "l"(__cvta_generic_to_global(src)), "r"((uint32_t)TILE_BYTES), "r"(mbar)
        : "memory");
}
DI void ldsm_x4(uint32_t* r, uint32_t addr) {
    asm volatile("ldmatrix.sync.aligned.m8n8.x4.shared.b16 {%0,%1,%2,%3}, [%4];"
                 : "=r"(r[0]), "=r"(r[1]), "=r"(r[2]), "=r"(r[3]) : "r"(addr));
}
DI void hmma(float* c, const uint32_t* a, uint32_t b0, uint32_t b1) {
    asm volatile(
        "mma.sync.aligned.m16n8k16.row.col.f32.f16.f16.f32 "
        "{%0,%1,%2,%3}, {%4,%5,%6,%7}, {%8,%9}, {%0,%1,%2,%3};"
        : "+f"(c[0]), "+f"(c[1]), "+f"(c[2]), "+f"(c[3])
        : "r"(a[0]), "r"(a[1]), "r"(a[2]), "r"(a[3]), "r"(b0), "r"(b1));
}
DI uint32_t pack_h2(float a, float b) {
    __half2 t = __floats2half2_rn(a, b);
    return *reinterpret_cast<uint32_t*>(&t);
}
DI uint4 quant8(float4 a, float4 b, float den, float lo, float hi2) {
    uint4 o;
    float q0 = fminf(fmaxf(rintf(a.x / den), lo), hi2);
    float q1 = fminf(fmaxf(rintf(a.y / den), lo), hi2);
    float q2 = fminf(fmaxf(rintf(a.z / den), lo), hi2);
    float q3 = fminf(fmaxf(rintf(a.w / den), lo), hi2);
    float q4 = fminf(fmaxf(rintf(b.x / den), lo), hi2);
    float q5 = fminf(fmaxf(rintf(b.y / den), lo), hi2);
    float q6 = fminf(fmaxf(rintf(b.z / den), lo), hi2);
    float q7 = fminf(fmaxf(rintf(b.w / den), lo), hi2);
    o.x = pack_h2(q0, q1);
    o.y = pack_h2(q2, q3);
    o.z = pack_h2(q4, q5);
    o.w = pack_h2(q6, q7);
    return o;
}

// ==================== quant stage 1 (unchanged) ====================

__global__ void k_prep(const float* __restrict__ w, const float* __restrict__ x) {
    const int t = threadIdx.x;
    if (blockIdx.x < 4096) {
        __shared__ double redd[256];
        const int row = blockIdx.x;
        const float4* p = reinterpret_cast<const float4*>(w + (size_t)row * 4096);
        float s0 = 0.f, s1 = 0.f, s2 = 0.f, s3 = 0.f;
#pragma unroll
        for (int j = 0; j < 4; ++j) {
            float4 v = p[t + j * 256];
            s0 += fabsf(v.x);
            s1 += fabsf(v.y);
            s2 += fabsf(v.z);
            s3 += fabsf(v.w);
        }
        redd[t] = (double)((s0 + s1) + (s2 + s3));
        __syncthreads();
        for (int st = 128; st > 0; st >>= 1) {
            if (t < st) redd[t] += redd[t + st];
            __syncthreads();
        }
        if (t == 0) g_part[row] = redd[0];
    } else {
        __shared__ float red[256];
        __shared__ float s_scale;
        const int row = blockIdx.x - 4096;
        const float4* p = reinterpret_cast<const float4*>(x + (size_t)row * 4096);
        float4 v[4];
        v[0] = p[2 * t];
        v[1] = p[2 * t + 1];
        v[2] = p[2 * t + 512];
        v[3] = p[2 * t + 513];
        float am = 0.f;
#pragma unroll
        for (int j = 0; j < 4; ++j)
            am = fmaxf(am, fmaxf(fmaxf(fabsf(v[j].x), fabsf(v[j].y)),
                                 fmaxf(fabsf(v[j].z), fabsf(v[j].w))));
        red[t] = am;
        __syncthreads();
        for (int st = 128; st > 0; st >>= 1) {
            if (t < st) red[t] = fmaxf(red[t], red[t + st]);
            __syncthreads();
        }
        if (t == 0) {
            float sc = fmaxf(red[0] / 127.0f, 1e-8f);
            s_scale = sc;
            g_sx[row] = sc;
        }
        __syncthreads();
        const float sc = s_scale;
        char* tbase = (char*)g_xq + (size_t)(row >> 7) * 64 * TILE_BYTES;
        const int rr = row & 127;
        const int sw = rr & 7;
#pragma unroll
        for (int j = 0; j < 2; ++j) {
            uint4 o = quant8(v[2 * j], v[2 * j + 1], sc, -127.f, 127.f);
            const int u = t + 256 * j;
            const int kc = u >> 3, c = u & 7;
            *reinterpret_cast<uint4*>(tbase + (size_t)kc * TILE_BYTES + rr * 128 +
                                      ((c ^ sw) << 4)) = o;
        }
    }
}

__global__ void k_wscale() {
    __shared__ double red[256];
    double s = 0.0;
#pragma unroll
    for (int j = 0; j < 16; ++j) s += g_part[threadIdx.x + j * 256];
    red[threadIdx.x] = s;
    __syncthreads();
    for (int st = 128; st > 0; st >>= 1) {
        if (threadIdx.x < st) red[threadIdx.x] += red[threadIdx.x + st];
        __syncthreads();
    }
    if (threadIdx.x == 0) {
        float sc = (float)(red[0] / 16777216.0);
        g_sw = sc;
        g_wdenom = sc + 1e-8f;
    }
}

__global__ void k_wq(const float* __restrict__ w) {
    const int t = threadIdx.x;
    const int row = blockIdx.x;
    const float4* p = reinterpret_cast<const float4*>(w + (size_t)row * 4096);
    float4 v[4];
    v[0] = p[2 * t];
    v[1] = p[2 * t + 1];
    v[2] = p[2 * t + 512];
    v[3] = p[2 * t + 513];
    const float d = g_wdenom;
    char* tbase = (char*)g_wq + (size_t)(row >> 7) * 64 * TILE_BYTES;
    const int rr = row & 127;
    const int sw = rr & 7;
#pragma unroll
    for (int j = 0; j < 2; ++j) {
        uint4 o = quant8(v[2 * j], v[2 * j + 1], d, -1.f, 1.f);
        const int u = t + 256 * j;
        const int kc = u >> 3, c = u & 7;
        *reinterpret_cast<uint4*>(tbase + (size_t)kc * TILE_BYTES + rr * 128 +
                                  ((c ^ sw) << 4)) = o;
    }
}

// ==================== GEMM ====================
// CTA 128x128x64, 4 warps (2m x 2n), warp tile 64x64, m16n8k16 HMMA, fp32 acc.
// 3-stage bulk-DMA ring. Fragments double-buffered across ks AND across the
// chunk boundary: full-wait for the next stage issues while the last hmma
// group drains, then next chunk's ks=0 fragments preload. Refill duty
// rotates across warps. 2 CTAs/SM.

__global__ void __launch_bounds__(128, 2) k_gemm(float* __restrict__ out) {
    extern __shared__ char smem[];
    const uint32_t sb = smem_u32(smem);
    const uint32_t mb = sb + SMEM_MBAR;           // full[3] @ +0,8,16 ; empty[3] @ +24,32,40
    const int tid = threadIdx.x, wid = tid >> 5, lane = tid & 31;
    const int wm = wid & 1, wn = wid >> 1;        // warp grid 2 (m) x 2 (n)

    const int nt = blockIdx.x & 31;               // n fast-varying: W stays L2-hot
    const int mt = blockIdx.x >> 5;

    if (tid == 0) {
#pragma unroll
        for (int s = 0; s < NSTAGE; ++s) {
            mbar_init(mb + s * 8, 1);             // full: producer expect_tx arrival
            mbar_init(mb + 24 + s * 8, 4);        // empty: 4 warp arrivals
        }
    }
    __syncthreads();

    const char* srcA = (const char*)g_xq + (size_t)mt * 64 * TILE_BYTES;
    const char* srcB = (const char*)g_wq + (size_t)nt * 64 * TILE_BYTES;

    if (tid == 0) {
#pragma unroll
        for (int s = 0; s < NSTAGE; ++s) {
            mbar_expect_tx(mb + s * 8, STAGE_BYTES);
            bulk16k(sb + s * STAGE_BYTES, srcA + (size_t)s * TILE_BYTES, mb + s * 8);
            bulk16k(sb + s * STAGE_BYTES + TILE_BYTES, srcB + (size_t)s * TILE_BYTES,
                    mb + s * 8);
        }
    }

    // fragment address precompute (pre-swizzled tiles: 16B col c' = c ^ (row&7))
    const int rowL = lane & 15, hi = lane >> 4;
    uint32_t abase[4], as6[4], bbase[4], bs6[4];
#pragma unroll
    for (int im = 0; im < 4; ++im) {
        const int r = wm * 64 + im * 16 + rowL;
        const int s = r & 7;
        abase[im] = (uint32_t)(r * 128 + ((hi ^ (s & 1)) << 4));
        as6[im] = (uint32_t)((s & 6) << 4);
    }
#pragma unroll
    for (int ib = 0; ib < 4; ++ib) {
        const int r = wn * 64 + ib * 16 + rowL;
        const int s = r & 7;
        bbase[ib] = (uint32_t)(TILE_BYTES + r * 128 + ((hi ^ (s & 1)) << 4));
        bs6[ib] = (uint32_t)((s & 6) << 4);
    }

    float acc[4][8][4];
#pragma unroll
    for (int i = 0; i < 4; ++i)
#pragma unroll
        for (int j = 0; j < 8; ++j)
#pragma unroll
            for (int q = 0; q < 4; ++q) acc[i][j][q] = 0.f;

    uint32_t afr[2][4][4], bfr[2][4][4];          // double-buffered fragments

#define LOAD_FRAG(STG, KS, BF)                                               \
    do {                                                                     \
        const uint32_t kterm_ = 32u * (KS);                                  \
        _Pragma("unroll")                                                    \
        for (int im_ = 0; im_ < 4; ++im_)                                    \
            ldsm_x4(afr[BF][im_], (STG) + abase[im_] + (kterm_ ^ as6[im_])); \
        _Pragma("unroll")                                                    \
        for (int ib_ = 0; ib_ < 4; ++ib_)                                    \
            ldsm_x4(bfr[BF][ib_], (STG) + bbase[ib_] + (kterm_ ^ bs6[ib_])); \
    } while (0)

    int stage = 0, phase = 0;
    mbar_wait(mb + 0, 0);
    LOAD_FRAG(sb, 0, 0);

    for (int kc = 0; kc < NCHUNK; ++kc) {
        const uint32_t stg = sb + stage * STAGE_BYTES;
        const int nstage = (stage + 1 == NSTAGE) ? 0 : stage + 1;
        const int nphase = (stage + 1 == NSTAGE) ? (phase ^ 1) : phase;

#pragma unroll
        for (int ks = 0; ks < 4; ++ks) {
            const int cur = ks & 1, nxt = cur ^ 1;
            if (ks < 3) LOAD_FRAG(stg, ks + 1, nxt);
#pragma unroll
            for (int im = 0; im < 4; ++im) {
#pragma unroll
                for (int in = 0; in < 8; ++in) {
                    const int ib = in >> 1, od = in & 1;
                    hmma(acc[im][in], afr[cur][im],
                         bfr[cur][ib][od ? 1 : 0], bfr[cur][ib][od ? 3 : 2]);
                }
            }
        }

        // all reads of this stage done (last hmma issued -> ldsm data consumed)
        if (lane == 0) mbar_arrive(mb + 24 + stage * 8);

        // boundary: wait for next stage while hmma drain, preload ks=0 frags
        if (kc + 1 < NCHUNK) {
            mbar_wait(mb + nstage * 8, nphase);
            LOAD_FRAG(sb + nstage * STAGE_BYTES, 0, 0);
        }

        // rotated producer: refill just-consumed stage for kc+NSTAGE
        if (kc + NSTAGE < NCHUNK && wid == (kc & 3) && lane == 0) {
            mbar_wait(mb + 24 + stage * 8, phase);
            mbar_expect_tx(mb + stage * 8, STAGE_BYTES);
            bulk16k(stg, srcA + (size_t)(kc + NSTAGE) * TILE_BYTES, mb + stage * 8);
            bulk16k(stg + TILE_BYTES, srcB + (size_t)(kc + NSTAGE) * TILE_BYTES,
                    mb + stage * 8);
        }

        stage = nstage;
        phase = nphase;
    }
#undef LOAD_FRAG

    // ---- epilogue: scale by sx[row]*sw and store ----
    const float swv = g_sw;
    const int row0 = mt * BM + wm * 64 + (lane >> 2);
    const int col0 = nt * BN + wn * 64 + 2 * (lane & 3);
#pragma unroll
    for (int im = 0; im < 4; ++im) {
        const int r = row0 + im * 16;
        const float f0 = g_sx[r] * swv;
        const float f8 = g_sx[r + 8] * swv;
        float* po0 = out + (size_t)r * N + col0;
        float* po8 = out + (size_t)(r + 8) * N + col0;
#pragma unroll
        for (int in = 0; in < 8; ++in) {
            float2 v0, v8;
            v0.x = acc[im][in][0] * f0;
            v0.y = acc[im][in][1] * f0;
            v8.x = acc[im][in][2] * f8;
            v8.y = acc[im][in][3] * f8;
            *reinterpret_cast<float2*>(po0 + in * 8) = v0;
            *reinterpret_cast<float2*>(po8 + in * 8) = v8;
        }
    }
}

// ==================== launch ====================
extern "C" void kernel_launch(void* const* d_in, const int* in_sizes, int n_in,
                              void* d_out, int out_size) {
    const float* x = (const float*)d_in[0];
    const float* w = (const float*)d_in[1];
    float* out = (float*)d_out;
    (void)in_sizes; (void)n_in; (void)out_size;

    k_prep<<<4096 + 8192, 256>>>(w, x);
    k_wscale<<<1, 256>>>();
    k_wq<<<4096, 256>>>(w);

    cudaFuncSetAttribute(k_gemm, cudaFuncAttributeMaxDynamicSharedMemorySize, SMEM_TOTAL);
    k_gemm<<<(M / BM) * (N / BN), 128, SMEM_TOTAL>>>(out);
}

// round 17
// speedup vs baseline: 1.4524x; 1.0231x over previous
#include <cuda_runtime.h>
#include <cuda_fp16.h>
#include <cstdint>

#define DI __device__ __forceinline__

// ---------------- problem sizes ----------------
static constexpr int M = 8192;
static constexpr int N = 4096;
static constexpr int K = 4096;

// ---------------- GEMM tiling ----------------
static constexpr int BM = 128;
static constexpr int BN = 128;
static constexpr int KC = 64;                     // halves per chunk = 128B rows
static constexpr int NCHUNK = K / KC;             // 64
static constexpr int NSTAGE = 3;
static constexpr int TILE_BYTES = 128 * 128;      // 16 KB tile (128 rows x 128B, swizzled)
static constexpr int STAGE_BYTES = 2 * TILE_BYTES;             // A + B
static constexpr int SMEM_MBAR = NSTAGE * STAGE_BYTES;         // 98304
static constexpr int SMEM_TOTAL = SMEM_MBAR + 64;              // + mbarriers -> 2 CTAs/SM

// ---------------- device scratch (tiled + swizzled layouts) ----------------
// g_xq: [mt(64)][kc(64)][rr(128)][sw16B(8)]  g_wq: [nt(32)][kc(64)][...]
__device__ __half g_xq[(size_t)M * K];
__device__ __half g_wq[(size_t)N * K];
__device__ float  g_sx[M];
__device__ double g_part[4096];
__device__ float  g_sw;
__device__ float  g_wdenom;

// ---------------- helpers ----------------
DI uint32_t smem_u32(const void* p) {
    uint32_t a;
    asm("{ .reg .u64 t; cvta.to.shared.u64 t, %1; cvt.u32.u64 %0, t; }" : "=r"(a) : "l"(p));
    return a;
}
DI void mbar_init(uint32_t addr, uint32_t cnt) {
    asm volatile("mbarrier.init.shared.b64 [%0], %1;" :: "r"(addr), "r"(cnt) : "memory");
}
DI void mbar_arrive(uint32_t addr) {
    asm volatile("mbarrier.arrive.shared.b64 _, [%0];" :: "r"(addr) : "memory");
}
DI void mbar_expect_tx(uint32_t addr, uint32_t bytes) {
    asm volatile("mbarrier.arrive.expect_tx.shared.b64 _, [%0], %1;"
                 :: "r"(addr), "r"(bytes) : "memory");
}
DI void mbar_wait(uint32_t addr, uint32_t parity) {
    asm volatile(
        "{\n\t.reg .pred P;\n\t"
        "WL%=:\n\t"
        "mbarrier.try_wait.parity.acquire.cta.shared::cta.b64 P, [%0], %1, 0x989680;\n\t"
        "@P bra.uni WD%=;\n\t"
        "bra.uni WL%=;\n\t"
        "WD%=:\n\t}"
        :: "r"(addr), "r"(parity) : "memory");
}
DI void bulk16k(uint32_t dst, const void* src, uint32_t mbar) {
    asm volatile(
        "cp.async.bulk.shared::cluster.global.mbarrier::complete_tx::bytes [%0], [%1], %2, [%3];"
        :: "r"(dst), "l"(__cvta_generic_to_global(src)), "r"((uint32_t)TILE_BYTES), "r"(mbar)
        : "memory");
}
DI void ldsm_x4(uint32_t* r, uint32_t addr) {
    asm volatile("ldmatrix.sync.aligned.m8n8.x4.shared.b16 {%0,%1,%2,%3}, [%4];"
                 : "=r"(r[0]), "=r"(r[1]), "=r"(r[2]), "=r"(r[3]) : "r"(addr));
}
DI void hmma(float* c, const uint32_t* a, uint32_t b0, uint32_t b1) {
    asm volatile(
        "mma.sync.aligned.m16n8k16.row.col.f32.f16.f16.f32 "
        "{%0,%1,%2,%3}, {%4,%5,%6,%7}, {%8,%9}, {%0,%1,%2,%3};"
        : "+f"(c[0]), "+f"(c[1]), "+f"(c[2]), "+f"(c[3])
        : "r"(a[0]), "r"(a[1]), "r"(a[2]), "r"(a[3]), "r"(b0), "r"(b1));
}
DI uint32_t pack_h2(float a, float b) {
    __half2 t = __floats2half2_rn(a, b);
    return *reinterpret_cast<uint32_t*>(&t);
}
DI uint4 quant8(float4 a, float4 b, float den, float lo, float hi2) {
    uint4 o;
    float q0 = fminf(fmaxf(rintf(a.x / den), lo), hi2);
    float q1 = fminf(fmaxf(rintf(a.y / den), lo), hi2);
    float q2 = fminf(fmaxf(rintf(a.z / den), lo), hi2);
    float q3 = fminf(fmaxf(rintf(a.w / den), lo), hi2);
    float q4 = fminf(fmaxf(rintf(b.x / den), lo), hi2);
    float q5 = fminf(fmaxf(rintf(b.y / den), lo), hi2);
    float q6 = fminf(fmaxf(rintf(b.z / den), lo), hi2);
    float q7 = fminf(fmaxf(rintf(b.w / den), lo), hi2);
    o.x = pack_h2(q0, q1);
    o.y = pack_h2(q2, q3);
    o.z = pack_h2(q4, q5);
    o.w = pack_h2(q6, q7);
    return o;
}

// ==================== quant stage 1 (unchanged) ====================

__global__ void k_prep(const float* __restrict__ w, const float* __restrict__ x) {
    const int t = threadIdx.x;
    if (blockIdx.x < 4096) {
        __shared__ double redd[256];
        const int row = blockIdx.x;
        const float4* p = reinterpret_cast<const float4*>(w + (size_t)row * 4096);
        float s0 = 0.f, s1 = 0.f, s2 = 0.f, s3 = 0.f;
#pragma unroll
        for (int j = 0; j < 4; ++j) {
            float4 v = p[t + j * 256];
            s0 += fabsf(v.x);
            s1 += fabsf(v.y);
            s2 += fabsf(v.z);
            s3 += fabsf(v.w);
        }
        redd[t] = (double)((s0 + s1) + (s2 + s3));
        __syncthreads();
        for (int st = 128; st > 0; st >>= 1) {
            if (t < st) redd[t] += redd[t + st];
            __syncthreads();
        }
        if (t == 0) g_part[row] = redd[0];
    } else {
        __shared__ float red[256];
        __shared__ float s_scale;
        const int row = blockIdx.x - 4096;
        const float4* p = reinterpret_cast<const float4*>(x + (size_t)row * 4096);
        float4 v[4];
        v[0] = p[2 * t];
        v[1] = p[2 * t + 1];
        v[2] = p[2 * t + 512];
        v[3] = p[2 * t + 513];
        float am = 0.f;
#pragma unroll
        for (int j = 0; j < 4; ++j)
            am = fmaxf(am, fmaxf(fmaxf(fabsf(v[j].x), fabsf(v[j].y)),
                                 fmaxf(fabsf(v[j].z), fabsf(v[j].w))));
        red[t] = am;
        __syncthreads();
        for (int st = 128; st > 0; st >>= 1) {
            if (t < st) red[t] = fmaxf(red[t], red[t + st]);
            __syncthreads();
        }
        if (t == 0) {
            float sc = fmaxf(red[0] / 127.0f, 1e-8f);
            s_scale = sc;
            g_sx[row] = sc;
        }
        __syncthreads();
        const float sc = s_scale;
        char* tbase = (char*)g_xq + (size_t)(row >> 7) * 64 * TILE_BYTES;
        const int rr = row & 127;
        const int sw = rr & 7;
#pragma unroll
        for (int j = 0; j < 2; ++j) {
            uint4 o = quant8(v[2 * j], v[2 * j + 1], sc, -127.f, 127.f);
            const int u = t + 256 * j;
            const int kc = u >> 3, c = u & 7;
            *reinterpret_cast<uint4*>(tbase + (size_t)kc * TILE_BYTES + rr * 128 +
                                      ((c ^ sw) << 4)) = o;
        }
    }
}

__global__ void k_wscale() {
    __shared__ double red[256];
    double s = 0.0;
#pragma unroll
    for (int j = 0; j < 16; ++j) s += g_part[threadIdx.x + j * 256];
    red[threadIdx.x] = s;
    __syncthreads();
    for (int st = 128; st > 0; st >>= 1) {
        if (threadIdx.x < st) red[threadIdx.x] += red[threadIdx.x + st];
        __syncthreads();
    }
    if (threadIdx.x == 0) {
        float sc = (float)(red[0] / 16777216.0);
        g_sw = sc;
        g_wdenom = sc + 1e-8f;
    }
}

__global__ void k_wq(const float* __restrict__ w) {
    const int t = threadIdx.x;
    const int row = blockIdx.x;
    const float4* p = reinterpret_cast<const float4*>(w + (size_t)row * 4096);
    float4 v[4];
    v[0] = p[2 * t];
    v[1] = p[2 * t + 1];
    v[2] = p[2 * t + 512];
    v[3] = p[2 * t + 513];
    const float d = g_wdenom;
    char* tbase = (char*)g_wq + (size_t)(row >> 7) * 64 * TILE_BYTES;
    const int rr = row & 127;
    const int sw = rr & 7;
#pragma unroll
    for (int j = 0; j < 2; ++j) {
        uint4 o = quant8(v[2 * j], v[2 * j + 1], d, -1.f, 1.f);
        const int u = t + 256 * j;
        const int kc = u >> 3, c = u & 7;
        *reinterpret_cast<uint4*>(tbase + (size_t)kc * TILE_BYTES + rr * 128 +
                                  ((c ^ sw) << 4)) = o;
    }
}

// ==================== GEMM ====================
// CTA 128x128x64, 4 warps (2m x 2n), warp tile 64x64, m16n8k16 HMMA, fp32 acc.
// 3-stage bulk-DMA ring. Fragments double-buffered across ks and across the
// chunk boundary. NEW: the boundary full-wait + next-chunk ks=0 preload issue
// BEFORE the last hmma group of the chunk, hiding TRYWAIT behind tensor-pipe
// drain. Refill duty rotates across warps. 2 CTAs/SM.

__global__ void __launch_bounds__(128, 2) k_gemm(float* __restrict__ out) {
    extern __shared__ char smem[];
    const uint32_t sb = smem_u32(smem);
    const uint32_t mb = sb + SMEM_MBAR;           // full[3] @ +0,8,16 ; empty[3] @ +24,32,40
    const int tid = threadIdx.x, wid = tid >> 5, lane = tid & 31;
    const int wm = wid & 1, wn = wid >> 1;        // warp grid 2 (m) x 2 (n)

    const int nt = blockIdx.x & 31;               // n fast-varying: W stays L2-hot
    const int mt = blockIdx.x >> 5;

    if (tid == 0) {
#pragma unroll
        for (int s = 0; s < NSTAGE; ++s) {
            mbar_init(mb + s * 8, 1);             // full: producer expect_tx arrival
            mbar_init(mb + 24 + s * 8, 4);        // empty: 4 warp arrivals
        }
    }
    __syncthreads();

    const char* srcA = (const char*)g_xq + (size_t)mt * 64 * TILE_BYTES;
    const char* srcB = (const char*)g_wq + (size_t)nt * 64 * TILE_BYTES;

    if (tid == 0) {
#pragma unroll
        for (int s = 0; s < NSTAGE; ++s) {
            mbar_expect_tx(mb + s * 8, STAGE_BYTES);
            bulk16k(sb + s * STAGE_BYTES, srcA + (size_t)s * TILE_BYTES, mb + s * 8);
            bulk16k(sb + s * STAGE_BYTES + TILE_BYTES, srcB + (size_t)s * TILE_BYTES,
                    mb + s * 8);
        }
    }

    // fragment address precompute (pre-swizzled tiles: 16B col c' = c ^ (row&7))
    const int rowL = lane & 15, hi = lane >> 4;
    uint32_t abase[4], as6[4], bbase[4], bs6[4];
#pragma unroll
    for (int im = 0; im < 4; ++im) {
        const int r = wm * 64 + im * 16 + rowL;
        const int s = r & 7;
        abase[im] = (uint32_t)(r * 128 + ((hi ^ (s & 1)) << 4));
        as6[im] = (uint32_t)((s & 6) << 4);
    }
#pragma unroll
    for (int ib = 0; ib < 4; ++ib) {
        const int r = wn * 64 + ib * 16 + rowL;
        const int s = r & 7;
        bbase[ib] = (uint32_t)(TILE_BYTES + r * 128 + ((hi ^ (s & 1)) << 4));
        bs6[ib] = (uint32_t)((s & 6) << 4);
    }

    float acc[4][8][4];
#pragma unroll
    for (int i = 0; i < 4; ++i)
#pragma unroll
        for (int j = 0; j < 8; ++j)
#pragma unroll
            for (int q = 0; q < 4; ++q) acc[i][j][q] = 0.f;

    uint32_t afr[2][4][4], bfr[2][4][4];          // double-buffered fragments

#define LOAD_FRAG(STG, KS, BF)                                               \
    do {                                                                     \
        const uint32_t kterm_ = 32u * (KS);                                  \
        _Pragma("unroll")                                                    \
        for (int im_ = 0; im_ < 4; ++im_)                                    \
            ldsm_x4(afr[BF][im_], (STG) + abase[im_] + (kterm_ ^ as6[im_])); \
        _Pragma("unroll")                                                    \
        for (int ib_ = 0; ib_ < 4; ++ib_)                                    \
            ldsm_x4(bfr[BF][ib_], (STG) + bbase[ib_] + (kterm_ ^ bs6[ib_])); \
    } while (0)

#define HMMA_GROUP(BF)                                                       \
    do {                                                                     \
        _Pragma("unroll")                                                    \
        for (int im_ = 0; im_ < 4; ++im_) {                                  \
            _Pragma("unroll")                                                \
            for (int in_ = 0; in_ < 8; ++in_) {                              \
                const int ib_ = in_ >> 1, od_ = in_ & 1;                     \
                hmma(acc[im_][in_], afr[BF][im_],                            \
                     bfr[BF][ib_][od_ ? 1 : 0], bfr[BF][ib_][od_ ? 3 : 2]);  \
            }                                                                \
        }                                                                    \
    } while (0)

    int stage = 0, phase = 0;
    mbar_wait(mb + 0, 0);
    LOAD_FRAG(sb, 0, 0);

    for (int kc = 0; kc < NCHUNK; ++kc) {
        const uint32_t stg = sb + stage * STAGE_BYTES;
        const int nstage = (stage + 1 == NSTAGE) ? 0 : stage + 1;
        const int nphase = (stage + 1 == NSTAGE) ? (phase ^ 1) : phase;

        // ks = 0..2: load next ks fragments, then hmma current
#pragma unroll
        for (int ks = 0; ks < 3; ++ks) {
            const int cur = ks & 1;
            LOAD_FRAG(stg, ks + 1, cur ^ 1);
            HMMA_GROUP(cur);
        }

        // all smem reads of this stage are issued (ks=3 frags are in regs)
        if (lane == 0) mbar_arrive(mb + 24 + stage * 8);

        // boundary wait + next-chunk ks=0 preload BEFORE the last hmma group:
        // TRYWAIT + 8 ldsm hide behind the tensor-pipe drain of ks=2/ks=3 groups.
        if (kc + 1 < NCHUNK) {
            mbar_wait(mb + nstage * 8, nphase);
            LOAD_FRAG(sb + nstage * STAGE_BYTES, 0, 0);   // into buf 0 (free: ks=2 consumed it)
        }

        HMMA_GROUP(1);                                    // ks = 3 (buf 1)

        // rotated producer: refill just-consumed stage for kc+NSTAGE
        if (kc + NSTAGE < NCHUNK && wid == (kc & 3) && lane == 0) {
            mbar_wait(mb + 24 + stage * 8, phase);
            mbar_expect_tx(mb + stage * 8, STAGE_BYTES);
            bulk16k(stg, srcA + (size_t)(kc + NSTAGE) * TILE_BYTES, mb + stage * 8);
            bulk16k(stg + TILE_BYTES, srcB + (size_t)(kc + NSTAGE) * TILE_BYTES,
                    mb + stage * 8);
        }

        stage = nstage;
        phase = nphase;
    }
#undef LOAD_FRAG
#undef HMMA_GROUP

    // ---- epilogue: scale by sx[row]*sw and store ----
    const float swv = g_sw;
    const int row0 = mt * BM + wm * 64 + (lane >> 2);
    const int col0 = nt * BN + wn * 64 + 2 * (lane & 3);
#pragma unroll
    for (int im = 0; im < 4; ++im) {
        const int r = row0 + im * 16;
        const float f0 = g_sx[r] * swv;
        const float f8 = g_sx[r + 8] * swv;
        float* po0 = out + (size_t)r * N + col0;
        float* po8 = out + (size_t)(r + 8) * N + col0;
#pragma unroll
        for (int in = 0; in < 8; ++in) {
            float2 v0, v8;
            v0.x = acc[im][in][0] * f0;
            v0.y = acc[im][in][1] * f0;
            v8.x = acc[im][in][2] * f8;
            v8.y = acc[im][in][3] * f8;
            *reinterpret_cast<float2*>(po0 + in * 8) = v0;
            *reinterpret_cast<float2*>(po8 + in * 8) = v8;
        }
    }
}

// ==================== launch ====================
extern "C" void kernel_launch(void* const* d_in, const int* in_sizes, int n_in,
                              void* d_out, int out_size) {
    const float* x = (const float*)d_in[0];
    const float* w = (const float*)d_in[1];
    float* out = (float*)d_out;
    (void)in_sizes; (void)n_in; (void)out_size;

    k_prep<<<4096 + 8192, 256>>>(w, x);
    k_wscale<<<1, 256>>>();
    k_wq<<<4096, 256>>>(w);

    cudaFuncSetAttribute(k_gemm, cudaFuncAttributeMaxDynamicSharedMemorySize, SMEM_TOTAL);
    k_gemm<<<(M / BM) * (N / BN), 128, SMEM_TOTAL>>>(out);
}